// round 2
// baseline (speedup 1.0000x reference)
#include <cuda_runtime.h>

#define BATCH 4
#define CCH   128
#define HH    128
#define WWID  128
#define NNODES (HH*WWID)
#define HEADS 8

// ---------------- scratch (static device globals; no allocation) ----------------
__device__ float g_xp  [BATCH * NNODES * CCH];    // [B][N][C] projected features
__device__ float g_asrc[BATCH * NNODES * HEADS];
__device__ float g_adst[BATCH * NNODES * HEADS];

// ---------------- Kernel A: xp = x_nodes @ W_lin ----------------
// x: [B][C][N] (channel-major), W: [C][128] row-major, xp: [B][N][128]
__global__ __launch_bounds__(256) void gemm_k(const float* __restrict__ x,
                                              const float* __restrict__ Wl) {
    __shared__ float As[16][128];
    __shared__ float Bs[16][128];

    const int b  = blockIdx.y;
    const int m0 = blockIdx.x * 128;
    const float* xb = x + (size_t)b * CCH * NNODES;

    const int tid = threadIdx.x;
    const int ty = tid >> 4;       // 0..15 : node group
    const int tx = tid & 15;       // 0..15 : k group

    float acc[8][8];
#pragma unroll
    for (int i = 0; i < 8; ++i)
#pragma unroll
        for (int j = 0; j < 8; ++j) acc[i][j] = 0.f;

    for (int kc = 0; kc < CCH; kc += 16) {
#pragma unroll
        for (int t = tid; t < 512; t += 256) {
            const int kk  = t >> 5;
            const int pos = (t & 31) << 2;
            *(float4*)&As[kk][pos] = *(const float4*)&xb[(size_t)(kc + kk) * NNODES + m0 + pos];
            *(float4*)&Bs[kk][pos] = *(const float4*)&Wl[(kc + kk) * CCH + pos];
        }
        __syncthreads();
#pragma unroll
        for (int kk = 0; kk < 16; ++kk) {
            float a[8], bb[8];
            *(float4*)&a[0]  = *(float4*)&As[kk][ty * 8];
            *(float4*)&a[4]  = *(float4*)&As[kk][ty * 8 + 4];
            *(float4*)&bb[0] = *(float4*)&Bs[kk][tx * 8];
            *(float4*)&bb[4] = *(float4*)&Bs[kk][tx * 8 + 4];
#pragma unroll
            for (int i = 0; i < 8; ++i)
#pragma unroll
                for (int j = 0; j < 8; ++j)
                    acc[i][j] = fmaf(a[i], bb[j], acc[i][j]);
        }
        __syncthreads();
    }

    float* outp = g_xp + (size_t)b * NNODES * CCH + (size_t)m0 * CCH;
#pragma unroll
    for (int i = 0; i < 8; ++i) {
        float* row = outp + (size_t)(ty * 8 + i) * CCH + tx * 8;
        float4 v0 = {acc[i][0], acc[i][1], acc[i][2], acc[i][3]};
        float4 v1 = {acc[i][4], acc[i][5], acc[i][6], acc[i][7]};
        *(float4*)&row[0] = v0;
        *(float4*)&row[4] = v1;
    }
}

// ---------------- Kernel B: per-node attention logits ----------------
// warp per node; lane covers 4 channels; heads are 16 consecutive channels
__global__ __launch_bounds__(256) void att_k(const float* __restrict__ att_src,
                                             const float* __restrict__ att_dst) {
    const int g    = blockIdx.x * 8 + (threadIdx.x >> 5);  // [0, B*N)
    const int lane = threadIdx.x & 31;

    const float4 v  = *(const float4*)&g_xp[(size_t)g * CCH + lane * 4];
    const float4 as = *(const float4*)&att_src[lane * 4];
    const float4 ad = *(const float4*)&att_dst[lane * 4];

    float ds = v.x * as.x + v.y * as.y + v.z * as.z + v.w * as.w;
    float dd = v.x * ad.x + v.y * ad.y + v.z * ad.z + v.w * ad.w;

    ds += __shfl_xor_sync(0xffffffffu, ds, 1);
    ds += __shfl_xor_sync(0xffffffffu, ds, 2);
    dd += __shfl_xor_sync(0xffffffffu, dd, 1);
    dd += __shfl_xor_sync(0xffffffffu, dd, 2);

    if ((lane & 3) == 0) {
        g_asrc[g * HEADS + (lane >> 2)] = ds;
        g_adst[g * HEADS + (lane >> 2)] = dd;
    }
}

// ---------------- Kernel C: softmax-stencil aggregate + bias + ELU + LN + transpose store ----------------
#define TR 4
#define TC 32
#define HC 34
#define HNODES (6 * 34)          // halo node-rows: (TR+2) x (TC+2)
#define OPITCH 132               // padded output row (floats)

#define SMEM_AGG ((HNODES * 128 + HNODES * 8 + 128 * 8 + 128 * OPITCH) * 4)

__global__ __launch_bounds__(256) void agg_k(const float* __restrict__ bias,
                                             const float* __restrict__ gamma,
                                             const float* __restrict__ beta,
                                             float* __restrict__ out) {
    extern __shared__ float sm[];
    float* s_xp  = sm;                          // [HNODES][128]
    float* s_as  = s_xp + HNODES * 128;         // [HNODES][8]
    float* s_ad  = s_as + HNODES * 8;           // [128][8]   (center nodes)
    float* s_out = s_ad + 128 * 8;              // [128][OPITCH]

    const int b  = blockIdx.z;
    const int r0 = blockIdx.y * TR;
    const int c0 = blockIdx.x * TC;
    const float* xpb = g_xp   + (size_t)b * NNODES * CCH;
    const float* asb = g_asrc + (size_t)b * NNODES * HEADS;
    const float* adb = g_adst + (size_t)b * NNODES * HEADS;

    // ---- load xp halo (zero-filled outside grid) ----
    for (int t = threadIdx.x; t < HNODES * 32; t += 256) {
        const int row = t >> 5;
        const int pos = (t & 31) << 2;
        const int hr = row / HC, hc = row - hr * HC;
        const int rg = r0 - 1 + hr, cg = c0 - 1 + hc;
        float4 v = {0.f, 0.f, 0.f, 0.f};
        if ((unsigned)rg < HH && (unsigned)cg < WWID)
            v = *(const float4*)&xpb[(size_t)(rg * WWID + cg) * CCH + pos];
        *(float4*)&s_xp[row * 128 + pos] = v;
    }
    // ---- load a_src halo ----
    for (int t = threadIdx.x; t < HNODES * 8; t += 256) {
        const int row = t >> 3;
        const int hr = row / HC, hc = row - hr * HC;
        const int rg = r0 - 1 + hr, cg = c0 - 1 + hc;
        float v = 0.f;
        if ((unsigned)rg < HH && (unsigned)cg < WWID)
            v = asb[(rg * WWID + cg) * HEADS + (t & 7)];
        s_as[t] = v;
    }
    // ---- load a_dst for center nodes ----
    for (int t = threadIdx.x; t < 128 * 8; t += 256) {
        const int node = t >> 3;
        const int lr = node >> 5, lc = node & 31;
        s_ad[t] = adb[((r0 + lr) * WWID + c0 + lc) * HEADS + (t & 7)];
    }
    __syncthreads();

    const int warp = threadIdx.x >> 5;
    const int lane = threadIdx.x & 31;
    const int h    = lane >> 2;        // head for this lane's 4 channels
    const int cch  = lane << 2;        // channel base

    const float4 bv = *(const float4*)&bias[cch];
    const float4 gv = *(const float4*)&gamma[cch];
    const float4 be = *(const float4*)&beta[cch];

#pragma unroll 1
    for (int i = 0; i < 16; ++i) {
        const int nl = warp * 16 + i;
        const int lr = nl >> 5, lc = nl & 31;
        const int rg = r0 + lr, cg = c0 + lc;

        const float adst = s_ad[nl * 8 + h];

        float e[9];
        float M = -1e30f;
#pragma unroll
        for (int m = 0; m < 9; ++m) {
            const int dr = m / 3 - 1, dc = m % 3 - 1;
            const int hrow = (lr + 1 + dr) * HC + (lc + 1 + dc);
            float sc = s_as[hrow * 8 + h] + adst;
            sc = sc > 0.f ? sc : 0.2f * sc;                 // leaky_relu(0.2)
            const bool ok = ((unsigned)(rg + dr) < HH) && ((unsigned)(cg + dc) < WWID);
            e[m] = ok ? sc : -1e30f;
            M = fmaxf(M, e[m]);
        }
        float den = 0.f;
#pragma unroll
        for (int m = 0; m < 9; ++m) { e[m] = __expf(e[m] - M); den += e[m]; }
        den += e[4];                                        // duplicated self-loop
        const float inv = 1.0f / den;

        float a0 = 0.f, a1 = 0.f, a2 = 0.f, a3 = 0.f;
#pragma unroll
        for (int m = 0; m < 9; ++m) {
            float w = e[m] * inv;
            if (m == 4) w += w;                             // self counted twice
            const int dr = m / 3 - 1, dc = m % 3 - 1;
            const int hrow = (lr + 1 + dr) * HC + (lc + 1 + dc);
            const float4 v = *(const float4*)&s_xp[hrow * 128 + cch];
            a0 = fmaf(w, v.x, a0);
            a1 = fmaf(w, v.y, a1);
            a2 = fmaf(w, v.z, a2);
            a3 = fmaf(w, v.w, a3);
        }
        // bias + ELU
        float o0 = a0 + bv.x, o1 = a1 + bv.y, o2 = a2 + bv.z, o3 = a3 + bv.w;
        o0 = o0 > 0.f ? o0 : expm1f(o0);
        o1 = o1 > 0.f ? o1 : expm1f(o1);
        o2 = o2 > 0.f ? o2 : expm1f(o2);
        o3 = o3 > 0.f ? o3 : expm1f(o3);
        // LayerNorm over 128 channels (warp allreduce)
        float sum = o0 + o1 + o2 + o3;
        float sq  = o0 * o0 + o1 * o1 + o2 * o2 + o3 * o3;
#pragma unroll
        for (int off = 16; off; off >>= 1) {
            sum += __shfl_xor_sync(0xffffffffu, sum, off);
            sq  += __shfl_xor_sync(0xffffffffu, sq,  off);
        }
        const float mu   = sum * 0.0078125f;
        const float var  = sq * 0.0078125f - mu * mu;
        const float rstd = rsqrtf(var + 1e-5f);

        float4 y;
        y.x = (o0 - mu) * rstd * gv.x + be.x;
        y.y = (o1 - mu) * rstd * gv.y + be.y;
        y.z = (o2 - mu) * rstd * gv.z + be.z;
        y.w = (o3 - mu) * rstd * gv.w + be.w;
        *(float4*)&s_out[nl * OPITCH + cch] = y;
    }
    __syncthreads();

    // ---- transposed, coalesced store: out[b][c][r][w] ----
    float* ob = out + (size_t)b * CCH * NNODES;
    for (int t = threadIdx.x; t < 128 * 128; t += 256) {
        const int c = t >> 7;
        const int node = t & 127;
        const int lr = node >> 5, lc = node & 31;
        ob[(size_t)c * NNODES + (r0 + lr) * WWID + c0 + lc] = s_out[node * OPITCH + c];
    }
}

// ---------------- launch ----------------
extern "C" void kernel_launch(void* const* d_in, const int* in_sizes, int n_in,
                              void* d_out, int out_size) {
    const float* x       = (const float*)d_in[0];
    const float* Wl      = (const float*)d_in[1];
    const float* att_src = (const float*)d_in[2];
    const float* att_dst = (const float*)d_in[3];
    const float* bias    = (const float*)d_in[4];
    const float* gamma   = (const float*)d_in[5];
    const float* beta    = (const float*)d_in[6];
    float* out = (float*)d_out;

    cudaFuncSetAttribute(agg_k, cudaFuncAttributeMaxDynamicSharedMemorySize, SMEM_AGG);

    gemm_k<<<dim3(NNODES / 128, BATCH), 256>>>(x, Wl);
    att_k<<<(BATCH * NNODES) / 8, 256>>>(att_src, att_dst);
    agg_k<<<dim3(WWID / TC, HH / TR, BATCH), 256, SMEM_AGG>>>(bias, gamma, beta, out);
}

// round 7
// speedup vs baseline: 1.2642x; 1.2642x over previous
#include <cuda_runtime.h>

#define BATCH 4
#define CCH   128
#define HH    128
#define WWID  128
#define NNODES (HH*WWID)
#define HEADS 8

typedef unsigned long long u64;

// ---------------- scratch (static device globals; no allocation) ----------------
__device__ float g_xp  [BATCH * NNODES * CCH];    // [B][N][C] projected features
__device__ float g_asrc[BATCH * NNODES * HEADS];
__device__ float g_adst[BATCH * NNODES * HEADS];

// ---------------- packed f32x2 helpers (sm_10x doubled-FP32 path) ----------------
__device__ __forceinline__ u64 pack2_dup(float x) {
    u64 r; unsigned xi = __float_as_uint(x);
    asm("mov.b64 %0, {%1, %1};" : "=l"(r) : "r"(xi));
    return r;
}
__device__ __forceinline__ u64 pack2(float lo, float hi) {
    u64 r;
    asm("mov.b64 %0, {%1, %2};" : "=l"(r)
        : "r"(__float_as_uint(lo)), "r"(__float_as_uint(hi)));
    return r;
}
__device__ __forceinline__ void fma2(u64& d, u64 a, u64 b) {
    asm("fma.rn.f32x2 %0, %1, %2, %0;" : "+l"(d) : "l"(a), "l"(b));
}
__device__ __forceinline__ float2 unpack2(u64 v) {
    unsigned lo, hi;
    asm("mov.b64 {%0, %1}, %2;" : "=r"(lo), "=r"(hi) : "l"(v));
    float2 f; f.x = __uint_as_float(lo); f.y = __uint_as_float(hi);
    return f;
}

// ---------------- Kernel A: xp = x_nodes @ W_lin  (+ fused attention logits) ----
// x: [B][C][N] (channel-major), W: [C][128] row-major, xp: [B][N][128]
__global__ __launch_bounds__(256) void gemm_k(const float* __restrict__ x,
                                              const float* __restrict__ Wl,
                                              const float* __restrict__ att_src,
                                              const float* __restrict__ att_dst) {
    __shared__ float As[16][128];
    __shared__ float Bs[16][128];

    const int b  = blockIdx.y;
    const int m0 = blockIdx.x * 128;
    const float* xb = x + (size_t)b * CCH * NNODES;

    const int tid = threadIdx.x;
    const int ty = tid >> 4;       // 0..15 : node group (8 rows each)
    const int tx = tid & 15;       // 0..15 : k group (8 cols each)

    u64 acc2[8][4];                // acc2[i][j] packs cols tx*8+2j, tx*8+2j+1
#pragma unroll
    for (int i = 0; i < 8; ++i)
#pragma unroll
        for (int j = 0; j < 4; ++j) acc2[i][j] = 0ull;

    for (int kc = 0; kc < CCH; kc += 16) {
#pragma unroll
        for (int t = tid; t < 512; t += 256) {
            const int kk  = t >> 5;
            const int pos = (t & 31) << 2;
            *(float4*)&As[kk][pos] = *(const float4*)&xb[(size_t)(kc + kk) * NNODES + m0 + pos];
            *(float4*)&Bs[kk][pos] = *(const float4*)&Wl[(kc + kk) * CCH + pos];
        }
        __syncthreads();
#pragma unroll
        for (int kk = 0; kk < 16; ++kk) {
            float a[8];
            *(float4*)&a[0] = *(float4*)&As[kk][ty * 8];
            *(float4*)&a[4] = *(float4*)&As[kk][ty * 8 + 4];
            float4 b0 = *(float4*)&Bs[kk][tx * 8];
            float4 b1 = *(float4*)&Bs[kk][tx * 8 + 4];
            u64 bp[4];
            bp[0] = pack2(b0.x, b0.y);
            bp[1] = pack2(b0.z, b0.w);
            bp[2] = pack2(b1.x, b1.y);
            bp[3] = pack2(b1.z, b1.w);
#pragma unroll
            for (int i = 0; i < 8; ++i) {
                const u64 ap = pack2_dup(a[i]);
#pragma unroll
                for (int j = 0; j < 4; ++j) fma2(acc2[i][j], ap, bp[j]);
            }
        }
        __syncthreads();
    }

    // ---- epilogue: store xp + fused attention logits ----
    float asv[8], adv[8];
    *(float4*)&asv[0] = *(const float4*)&att_src[tx * 8];
    *(float4*)&asv[4] = *(const float4*)&att_src[tx * 8 + 4];
    *(float4*)&adv[0] = *(const float4*)&att_dst[tx * 8];
    *(float4*)&adv[4] = *(const float4*)&att_dst[tx * 8 + 4];

    float* outp = g_xp + ((size_t)b * NNODES + m0 + ty * 8) * CCH + tx * 8;
#pragma unroll
    for (int i = 0; i < 8; ++i) {
        float v[8];
#pragma unroll
        for (int j = 0; j < 4; ++j) {
            float2 p = unpack2(acc2[i][j]);
            v[2 * j] = p.x; v[2 * j + 1] = p.y;
        }
        *(float4*)&outp[(size_t)i * CCH]     = *(float4*)&v[0];
        *(float4*)&outp[(size_t)i * CCH + 4] = *(float4*)&v[4];

        float s = 0.f, d = 0.f;
#pragma unroll
        for (int j = 0; j < 8; ++j) { s = fmaf(v[j], asv[j], s); d = fmaf(v[j], adv[j], d); }
        // partner thread (tx^1) holds the other 8 channels of this 16-wide head
        s += __shfl_xor_sync(0xffffffffu, s, 1);
        d += __shfl_xor_sync(0xffffffffu, d, 1);
        if ((tx & 1) == 0) {
            const int n = m0 + ty * 8 + i;
            g_asrc[((size_t)b * NNODES + n) * HEADS + (tx >> 1)] = s;
            g_adst[((size_t)b * NNODES + n) * HEADS + (tx >> 1)] = d;
        }
    }
}

// ---------------- Kernel C: softmax-stencil aggregate + bias + ELU + LN + transpose store ----------------
#define TR 4
#define TC 32
#define HC 34
#define HNODES (6 * 34)          // halo node-rows: (TR+2) x (TC+2)
#define OPITCH 132               // padded output row (floats)
#define AGG_THREADS 512

#define SMEM_AGG ((HNODES * 128 + HNODES * 8 + 128 * 8 + 128 * OPITCH) * 4)

__global__ __launch_bounds__(AGG_THREADS) void agg_k(const float* __restrict__ bias,
                                                     const float* __restrict__ gamma,
                                                     const float* __restrict__ beta,
                                                     float* __restrict__ out) {
    extern __shared__ float sm[];
    float* s_xp  = sm;                          // [HNODES][128]
    float* s_as  = s_xp + HNODES * 128;         // [HNODES][8]
    float* s_ad  = s_as + HNODES * 8;           // [128][8]   (center nodes)
    float* s_out = s_ad + 128 * 8;              // [128][OPITCH]

    const int b  = blockIdx.z;
    const int r0 = blockIdx.y * TR;
    const int c0 = blockIdx.x * TC;
    const float* xpb = g_xp   + (size_t)b * NNODES * CCH;
    const float* asb = g_asrc + (size_t)b * NNODES * HEADS;
    const float* adb = g_adst + (size_t)b * NNODES * HEADS;

    // ---- load xp halo (zero-filled outside grid) ----
    for (int t = threadIdx.x; t < HNODES * 32; t += AGG_THREADS) {
        const int row = t >> 5;
        const int pos = (t & 31) << 2;
        const int hr = row / HC, hc = row - hr * HC;
        const int rg = r0 - 1 + hr, cg = c0 - 1 + hc;
        float4 v = {0.f, 0.f, 0.f, 0.f};
        if ((unsigned)rg < HH && (unsigned)cg < WWID)
            v = *(const float4*)&xpb[(size_t)(rg * WWID + cg) * CCH + pos];
        *(float4*)&s_xp[row * 128 + pos] = v;
    }
    // ---- load a_src halo ----
    for (int t = threadIdx.x; t < HNODES * 8; t += AGG_THREADS) {
        const int row = t >> 3;
        const int hr = row / HC, hc = row - hr * HC;
        const int rg = r0 - 1 + hr, cg = c0 - 1 + hc;
        float v = 0.f;
        if ((unsigned)rg < HH && (unsigned)cg < WWID)
            v = asb[(rg * WWID + cg) * HEADS + (t & 7)];
        s_as[t] = v;
    }
    // ---- load a_dst for center nodes ----
    for (int t = threadIdx.x; t < 128 * 8; t += AGG_THREADS) {
        const int node = t >> 3;
        const int lr = node >> 5, lc = node & 31;
        s_ad[t] = adb[((r0 + lr) * WWID + c0 + lc) * HEADS + (t & 7)];
    }
    __syncthreads();

    const int warp = threadIdx.x >> 5;   // 0..15, each handles 8 nodes
    const int lane = threadIdx.x & 31;
    const int h    = lane >> 2;          // head for this lane's 4 channels
    const int cch  = lane << 2;          // channel base

    const float4 bv = *(const float4*)&bias[cch];
    const float4 gv = *(const float4*)&gamma[cch];
    const float4 be = *(const float4*)&beta[cch];

#pragma unroll 1
    for (int i = 0; i < 8; ++i) {
        const int nl = warp * 8 + i;
        const int lr = nl >> 5, lc = nl & 31;
        const int rg = r0 + lr, cg = c0 + lc;

        const float adst = s_ad[nl * 8 + h];

        float e[9];
        float M = -1e30f;
#pragma unroll
        for (int m = 0; m < 9; ++m) {
            const int dr = m / 3 - 1, dc = m % 3 - 1;
            const int hrow = (lr + 1 + dr) * HC + (lc + 1 + dc);
            float sc = s_as[hrow * 8 + h] + adst;
            sc = sc > 0.f ? sc : 0.2f * sc;                 // leaky_relu(0.2)
            const bool ok = ((unsigned)(rg + dr) < HH) && ((unsigned)(cg + dc) < WWID);
            e[m] = ok ? sc : -1e30f;
            M = fmaxf(M, e[m]);
        }
        float den = 0.f;
#pragma unroll
        for (int m = 0; m < 9; ++m) { e[m] = __expf(e[m] - M); den += e[m]; }
        den += e[4];                                        // duplicated self-loop
        const float inv = __fdividef(1.0f, den);

        float a0 = 0.f, a1 = 0.f, a2 = 0.f, a3 = 0.f;
#pragma unroll
        for (int m = 0; m < 9; ++m) {
            float w = e[m] * inv;
            if (m == 4) w += w;                             // self counted twice
            const int dr = m / 3 - 1, dc = m % 3 - 1;
            const int hrow = (lr + 1 + dr) * HC + (lc + 1 + dc);
            const float4 v = *(const float4*)&s_xp[hrow * 128 + cch];
            a0 = fmaf(w, v.x, a0);
            a1 = fmaf(w, v.y, a1);
            a2 = fmaf(w, v.z, a2);
            a3 = fmaf(w, v.w, a3);
        }
        // bias + ELU (elu(x) = exp(x)-1 for x<0)
        float o0 = a0 + bv.x, o1 = a1 + bv.y, o2 = a2 + bv.z, o3 = a3 + bv.w;
        o0 = o0 > 0.f ? o0 : (__expf(o0) - 1.f);
        o1 = o1 > 0.f ? o1 : (__expf(o1) - 1.f);
        o2 = o2 > 0.f ? o2 : (__expf(o2) - 1.f);
        o3 = o3 > 0.f ? o3 : (__expf(o3) - 1.f);
        // LayerNorm over 128 channels (warp allreduce)
        float sum = o0 + o1 + o2 + o3;
        float sq  = o0 * o0 + o1 * o1 + o2 * o2 + o3 * o3;
#pragma unroll
        for (int off = 16; off; off >>= 1) {
            sum += __shfl_xor_sync(0xffffffffu, sum, off);
            sq  += __shfl_xor_sync(0xffffffffu, sq,  off);
        }
        const float mu   = sum * 0.0078125f;
        const float var  = sq * 0.0078125f - mu * mu;
        const float rstd = rsqrtf(var + 1e-5f);

        float4 y;
        y.x = (o0 - mu) * rstd * gv.x + be.x;
        y.y = (o1 - mu) * rstd * gv.y + be.y;
        y.z = (o2 - mu) * rstd * gv.z + be.z;
        y.w = (o3 - mu) * rstd * gv.w + be.w;
        *(float4*)&s_out[nl * OPITCH + cch] = y;
    }
    __syncthreads();

    // ---- transposed, coalesced store: out[b][c][r][w] ----
    float* ob = out + (size_t)b * CCH * NNODES;
    for (int t = threadIdx.x; t < 128 * 128; t += AGG_THREADS) {
        const int c = t >> 7;
        const int node = t & 127;
        const int lr = node >> 5, lc = node & 31;
        ob[(size_t)c * NNODES + (r0 + lr) * WWID + c0 + lc] = s_out[node * OPITCH + c];
    }
}

// ---------------- launch ----------------
extern "C" void kernel_launch(void* const* d_in, const int* in_sizes, int n_in,
                              void* d_out, int out_size) {
    const float* x       = (const float*)d_in[0];
    const float* Wl      = (const float*)d_in[1];
    const float* att_src = (const float*)d_in[2];
    const float* att_dst = (const float*)d_in[3];
    const float* bias    = (const float*)d_in[4];
    const float* gamma   = (const float*)d_in[5];
    const float* beta    = (const float*)d_in[6];
    float* out = (float*)d_out;

    cudaFuncSetAttribute(agg_k, cudaFuncAttributeMaxDynamicSharedMemorySize, SMEM_AGG);

    gemm_k<<<dim3(NNODES / 128, BATCH), 256>>>(x, Wl, att_src, att_dst);
    agg_k<<<dim3(WWID / TC, HH / TR, BATCH), AGG_THREADS, SMEM_AGG>>>(bias, gamma, beta, out);
}

// round 10
// speedup vs baseline: 1.5270x; 1.2079x over previous
#include <cuda_runtime.h>

#define BATCH 4
#define CCH   128
#define HH    128
#define WWID  128
#define NNODES (HH*WWID)
#define HEADS 8

typedef unsigned long long u64;

// ---------------- scratch (static device globals; no allocation) ----------------
__device__ float g_xp  [BATCH * NNODES * CCH];    // [B][N][C] projected features
__device__ float g_asrc[BATCH * NNODES * HEADS];
__device__ float g_adst[BATCH * NNODES * HEADS];

// ---------------- packed f32x2 helpers (sm_10x doubled-FP32 path) ----------------
__device__ __forceinline__ u64 pack2_dup(float x) {
    u64 r; unsigned xi = __float_as_uint(x);
    asm("mov.b64 %0, {%1, %1};" : "=l"(r) : "r"(xi));
    return r;
}
__device__ __forceinline__ void fma2(u64& d, u64 a, u64 b) {
    asm("fma.rn.f32x2 %0, %1, %2, %0;" : "+l"(d) : "l"(a), "l"(b));
}
__device__ __forceinline__ float2 unpack2(u64 v) {
    unsigned lo, hi;
    asm("mov.b64 {%0, %1}, %2;" : "=r"(lo), "=r"(hi) : "l"(v));
    float2 f; f.x = __uint_as_float(lo); f.y = __uint_as_float(hi);
    return f;
}

// ---------------- Kernel A: xp = x_nodes @ W_lin  (+ fused attention logits) ----
// x: [B][C][N] (channel-major), W: [C][128] row-major, xp: [B][N][128]
__global__ __launch_bounds__(256) void gemm_k(const float* __restrict__ x,
                                              const float* __restrict__ Wl,
                                              const float* __restrict__ att_src,
                                              const float* __restrict__ att_dst) {
    __shared__ float As[16][128];
    __shared__ float Bs[16][128];

    const int b  = blockIdx.y;
    const int m0 = blockIdx.x * 128;
    const float* xb = x + (size_t)b * CCH * NNODES;

    const int tid = threadIdx.x;
    const int ty = tid >> 4;       // 0..15 : node group (8 rows each)
    const int tx = tid & 15;       // 0..15 : k group (8 cols each)

    u64 acc2[8][4];                // acc2[i][j] packs cols tx*8+2j, tx*8+2j+1
#pragma unroll
    for (int i = 0; i < 8; ++i)
#pragma unroll
        for (int j = 0; j < 4; ++j) acc2[i][j] = 0ull;

    for (int kc = 0; kc < CCH; kc += 16) {
#pragma unroll
        for (int t = tid; t < 512; t += 256) {
            const int kk  = t >> 5;
            const int pos = (t & 31) << 2;
            *(float4*)&As[kk][pos] = *(const float4*)&xb[(size_t)(kc + kk) * NNODES + m0 + pos];
            *(float4*)&Bs[kk][pos] = *(const float4*)&Wl[(kc + kk) * CCH + pos];
        }
        __syncthreads();
#pragma unroll
        for (int kk = 0; kk < 16; ++kk) {
            float a[8];
            *(float4*)&a[0] = *(float4*)&As[kk][ty * 8];
            *(float4*)&a[4] = *(float4*)&As[kk][ty * 8 + 4];
            // adjacent Bs columns are already a packed f32x2 pair in SMEM
            const ulonglong2 bq0 = *(const ulonglong2*)&Bs[kk][tx * 8];
            const ulonglong2 bq1 = *(const ulonglong2*)&Bs[kk][tx * 8 + 4];
            u64 bp[4];
            bp[0] = bq0.x; bp[1] = bq0.y; bp[2] = bq1.x; bp[3] = bq1.y;
#pragma unroll
            for (int i = 0; i < 8; ++i) {
                const u64 ap = pack2_dup(a[i]);
#pragma unroll
                for (int j = 0; j < 4; ++j) fma2(acc2[i][j], ap, bp[j]);
            }
        }
        __syncthreads();
    }

    // ---- epilogue: store xp + fused attention logits ----
    float asv[8], adv[8];
    *(float4*)&asv[0] = *(const float4*)&att_src[tx * 8];
    *(float4*)&asv[4] = *(const float4*)&att_src[tx * 8 + 4];
    *(float4*)&adv[0] = *(const float4*)&att_dst[tx * 8];
    *(float4*)&adv[4] = *(const float4*)&att_dst[tx * 8 + 4];

    float* outp = g_xp + ((size_t)b * NNODES + m0 + ty * 8) * CCH + tx * 8;
#pragma unroll
    for (int i = 0; i < 8; ++i) {
        float v[8];
#pragma unroll
        for (int j = 0; j < 4; ++j) {
            float2 p = unpack2(acc2[i][j]);
            v[2 * j] = p.x; v[2 * j + 1] = p.y;
        }
        *(float4*)&outp[(size_t)i * CCH]     = *(float4*)&v[0];
        *(float4*)&outp[(size_t)i * CCH + 4] = *(float4*)&v[4];

        float s = 0.f, d = 0.f;
#pragma unroll
        for (int j = 0; j < 8; ++j) { s = fmaf(v[j], asv[j], s); d = fmaf(v[j], adv[j], d); }
        // partner thread (tx^1) holds the other 8 channels of this 16-wide head
        s += __shfl_xor_sync(0xffffffffu, s, 1);
        d += __shfl_xor_sync(0xffffffffu, d, 1);
        if ((tx & 1) == 0) {
            const int n = m0 + ty * 8 + i;
            g_asrc[((size_t)b * NNODES + n) * HEADS + (tx >> 1)] = s;
            g_adst[((size_t)b * NNODES + n) * HEADS + (tx >> 1)] = d;
        }
    }
}

// ---------------- Kernel C: softmax-stencil aggregate + bias + ELU + LN + transpose store ----------------
// 8x8 spatial tile (64 nodes), 10x10 halo, 512 threads = 16 warps x 4 nodes.
// SMEM = 88.1 KB  ->  2 CTAs/SM resident (occupancy fix for latency hiding).
#define TR 8
#define TC 8
#define HC 10
#define HNODES (10 * 10)         // halo node-rows: (TR+2) x (TC+2)
#define TNODES (TR * TC)         // 64 center nodes
#define OPITCH 132               // padded pitch; multiple of 4 -> float4-aligned stores
#define AGG_THREADS 512

#define SMEM_AGG ((HNODES * 128 + HNODES * 8 + TNODES * 8 + TNODES * OPITCH) * 4)

__global__ __launch_bounds__(AGG_THREADS, 2) void agg_k(const float* __restrict__ bias,
                                                        const float* __restrict__ gamma,
                                                        const float* __restrict__ beta,
                                                        float* __restrict__ out) {
    extern __shared__ float sm[];
    float* s_xp  = sm;                          // [HNODES][128]
    float* s_as  = s_xp + HNODES * 128;         // [HNODES][8]
    float* s_ad  = s_as + HNODES * 8;           // [TNODES][8]   (center nodes)
    float* s_out = s_ad + TNODES * 8;           // [TNODES][OPITCH]

    const int b  = blockIdx.z;
    const int r0 = blockIdx.y * TR;
    const int c0 = blockIdx.x * TC;
    const float* xpb = g_xp   + (size_t)b * NNODES * CCH;
    const float* asb = g_asrc + (size_t)b * NNODES * HEADS;
    const float* adb = g_adst + (size_t)b * NNODES * HEADS;

    // ---- load xp halo (zero-filled outside grid) ----
    for (int t = threadIdx.x; t < HNODES * 32; t += AGG_THREADS) {
        const int row = t >> 5;
        const int pos = (t & 31) << 2;
        const int hr = row / HC, hc = row - hr * HC;
        const int rg = r0 - 1 + hr, cg = c0 - 1 + hc;
        float4 v = {0.f, 0.f, 0.f, 0.f};
        if ((unsigned)rg < HH && (unsigned)cg < WWID)
            v = *(const float4*)&xpb[(size_t)(rg * WWID + cg) * CCH + pos];
        *(float4*)&s_xp[row * 128 + pos] = v;
    }
    // ---- load a_src halo ----
    for (int t = threadIdx.x; t < HNODES * 8; t += AGG_THREADS) {
        const int row = t >> 3;
        const int hr = row / HC, hc = row - hr * HC;
        const int rg = r0 - 1 + hr, cg = c0 - 1 + hc;
        float v = 0.f;
        if ((unsigned)rg < HH && (unsigned)cg < WWID)
            v = asb[(rg * WWID + cg) * HEADS + (t & 7)];
        s_as[t] = v;
    }
    // ---- load a_dst for center nodes ----
    for (int t = threadIdx.x; t < TNODES * 8; t += AGG_THREADS) {
        const int node = t >> 3;
        const int lr = node >> 3, lc = node & 7;
        s_ad[t] = adb[((r0 + lr) * WWID + c0 + lc) * HEADS + (t & 7)];
    }
    __syncthreads();

    const int warp = threadIdx.x >> 5;   // 0..15, each handles 4 nodes
    const int lane = threadIdx.x & 31;
    const int h    = lane >> 2;          // head for this lane's 4 channels
    const int cch  = lane << 2;          // channel base

    const float4 bv = *(const float4*)&bias[cch];
    const float4 gv = *(const float4*)&gamma[cch];
    const float4 be = *(const float4*)&beta[cch];

#pragma unroll 1
    for (int i = 0; i < 4; ++i) {
        const int nl = warp * 4 + i;
        const int lr = nl >> 3, lc = nl & 7;
        const int rg = r0 + lr, cg = c0 + lc;

        const float adst = s_ad[nl * 8 + h];

        float e[9];
        float M = -1e30f;
#pragma unroll
        for (int m = 0; m < 9; ++m) {
            const int dr = m / 3 - 1, dc = m % 3 - 1;
            const int hrow = (lr + 1 + dr) * HC + (lc + 1 + dc);
            float sc = s_as[hrow * 8 + h] + adst;
            sc = sc > 0.f ? sc : 0.2f * sc;                 // leaky_relu(0.2)
            const bool ok = ((unsigned)(rg + dr) < HH) && ((unsigned)(cg + dc) < WWID);
            e[m] = ok ? sc : -1e30f;
            M = fmaxf(M, e[m]);
        }
        float den = 0.f;
#pragma unroll
        for (int m = 0; m < 9; ++m) { e[m] = __expf(e[m] - M); den += e[m]; }
        den += e[4];                                        // duplicated self-loop
        const float inv = __fdividef(1.0f, den);

        float a0 = 0.f, a1 = 0.f, a2 = 0.f, a3 = 0.f;
#pragma unroll
        for (int m = 0; m < 9; ++m) {
            float w = e[m] * inv;
            if (m == 4) w += w;                             // self counted twice
            const int dr = m / 3 - 1, dc = m % 3 - 1;
            const int hrow = (lr + 1 + dr) * HC + (lc + 1 + dc);
            const float4 v = *(const float4*)&s_xp[hrow * 128 + cch];
            a0 = fmaf(w, v.x, a0);
            a1 = fmaf(w, v.y, a1);
            a2 = fmaf(w, v.z, a2);
            a3 = fmaf(w, v.w, a3);
        }
        // bias + ELU (elu(x) = exp(x)-1 for x<0)
        float o0 = a0 + bv.x, o1 = a1 + bv.y, o2 = a2 + bv.z, o3 = a3 + bv.w;
        o0 = o0 > 0.f ? o0 : (__expf(o0) - 1.f);
        o1 = o1 > 0.f ? o1 : (__expf(o1) - 1.f);
        o2 = o2 > 0.f ? o2 : (__expf(o2) - 1.f);
        o3 = o3 > 0.f ? o3 : (__expf(o3) - 1.f);
        // LayerNorm over 128 channels (warp allreduce)
        float sum = o0 + o1 + o2 + o3;
        float sq  = o0 * o0 + o1 * o1 + o2 * o2 + o3 * o3;
#pragma unroll
        for (int off = 16; off; off >>= 1) {
            sum += __shfl_xor_sync(0xffffffffu, sum, off);
            sq  += __shfl_xor_sync(0xffffffffu, sq,  off);
        }
        const float mu   = sum * 0.0078125f;
        const float var  = sq * 0.0078125f - mu * mu;
        const float rstd = rsqrtf(var + 1e-5f);

        float4 y;
        y.x = (o0 - mu) * rstd * gv.x + be.x;
        y.y = (o1 - mu) * rstd * gv.y + be.y;
        y.z = (o2 - mu) * rstd * gv.z + be.z;
        y.w = (o3 - mu) * rstd * gv.w + be.w;
        *(float4*)&s_out[nl * OPITCH + cch] = y;
    }
    __syncthreads();

    // ---- transposed store: out[b][c][r][w]  (8-float runs, full 32B sectors) ----
    float* ob = out + (size_t)b * CCH * NNODES;
    for (int t = threadIdx.x; t < CCH * TNODES; t += AGG_THREADS) {
        const int c = t >> 6;          // 0..127
        const int node = t & 63;       // 0..63
        const int lr = node >> 3, lc = node & 7;
        ob[(size_t)c * NNODES + (r0 + lr) * WWID + c0 + lc] = s_out[node * OPITCH + c];
    }
}

// ---------------- launch ----------------
extern "C" void kernel_launch(void* const* d_in, const int* in_sizes, int n_in,
                              void* d_out, int out_size) {
    const float* x       = (const float*)d_in[0];
    const float* Wl      = (const float*)d_in[1];
    const float* att_src = (const float*)d_in[2];
    const float* att_dst = (const float*)d_in[3];
    const float* bias    = (const float*)d_in[4];
    const float* gamma   = (const float*)d_in[5];
    const float* beta    = (const float*)d_in[6];
    float* out = (float*)d_out;

    cudaFuncSetAttribute(agg_k, cudaFuncAttributeMaxDynamicSharedMemorySize, SMEM_AGG);

    gemm_k<<<dim3(NNODES / 128, BATCH), 256>>>(x, Wl, att_src, att_dst);
    agg_k<<<dim3(WWID / TC, HH / TR, BATCH), AGG_THREADS, SMEM_AGG>>>(bias, gamma, beta, out);
}

// round 13
// speedup vs baseline: 1.5999x; 1.0477x over previous
#include <cuda_runtime.h>
#include <cuda_bf16.h>
#include <cstdint>

#define BATCH 4
#define CCH   128
#define HH    128
#define WWID  128
#define NNODES (HH*WWID)
#define HEADS 8

typedef unsigned int u32;

// ---------------- scratch (static device globals; no allocation) ----------------
__device__ float g_xp  [BATCH * NNODES * CCH];    // [B][N][C] projected features
__device__ float g_asrc[BATCH * NNODES * HEADS];
__device__ float g_adst[BATCH * NNODES * HEADS];
// Pre-baked W fragments for mma.sync m16n8k16 (A-operand = W^T, row-major [m=c_out][k=c_in])
// layout: [hi(0)/lo(1)][tile = kt*8+mt][lane 0..31][reg 0..3]  (u32 bf16x2)
__device__ u32 g_Wfrag[2 * 64 * 32 * 4];

// ---------------- mma.sync bf16 (sm_80+ path; compiles under compute_103) ----------------
__device__ __forceinline__ void mma_bf16(float* c, const u32* a, const u32* b) {
    asm volatile("mma.sync.aligned.m16n8k16.row.col.f32.bf16.bf16.f32 "
                 "{%0,%1,%2,%3}, {%4,%5,%6,%7}, {%8,%9}, {%0,%1,%2,%3};"
                 : "+f"(c[0]), "+f"(c[1]), "+f"(c[2]), "+f"(c[3])
                 : "r"(a[0]), "r"(a[1]), "r"(a[2]), "r"(a[3]),
                   "r"(b[0]), "r"(b[1]));
}

// ---------------- Kernel P: bake W^T hi/lo mma fragments ----------------
// A[m][k] = Wl[k*128 + m].  m16n8k16 A-frag: a0:(m=l/4, k=2(l%4)+{0,1}),
// a1:(m+8, k), a2:(m, k+8), a3:(m+8, k+8); bf16x2 low half = even k.
__global__ __launch_bounds__(256) void bprep_k(const float* __restrict__ Wl) {
    const int g  = blockIdx.x * 256 + threadIdx.x;   // 0..2047
    const int kt = g >> 8;
    const int mt = (g >> 5) & 7;
    const int l  = g & 31;
    const int base = ((kt * 8 + mt) * 32 + l) * 4;
#pragma unroll
    for (int r = 0; r < 4; ++r) {
        const int m = mt * 16 + (l >> 2) + (r & 1) * 8;
        const int k = kt * 16 + (l & 3) * 2 + (r >> 1) * 8;
        const float v0 = Wl[k * CCH + m];
        const float v1 = Wl[(k + 1) * CCH + m];
        const __nv_bfloat16 h0 = __float2bfloat16(v0);
        const __nv_bfloat16 h1 = __float2bfloat16(v1);
        const __nv_bfloat16 l0 = __float2bfloat16(v0 - __bfloat162float(h0));
        const __nv_bfloat16 l1 = __float2bfloat16(v1 - __bfloat162float(h1));
        g_Wfrag[base + r]        = (u32)__bfloat16_as_ushort(h0) | ((u32)__bfloat16_as_ushort(h1) << 16);
        g_Wfrag[8192 + base + r] = (u32)__bfloat16_as_ushort(l0) | ((u32)__bfloat16_as_ushort(l1) << 16);
    }
}

// ---------------- Kernel A: bf16x3 HMMA GEMM (C^T form) + fused attention logits ----
// D[c_out][node] = W^T @ x_tile.  B-operand = x in native [k][n] layout (no transpose).
#define XP_PITCH 136                       // u32 words per kp-row: 136%32=8 -> conflict-free B frags
#define SOFF_WFRAG 0                       // 65536 B
#define SOFF_XH    65536                   // 64*136*4 = 34816 B
#define SOFF_XL    (65536 + 34816)
#define SOFF_OUT   65536                   // reuse Xp region after mma
#define OUT_PITCH  132                     // floats; 132%32=4 -> conflict-free frag stores
#define SMEM_MMA   (65536 + 2 * 34816)

__global__ __launch_bounds__(256) void mma_k(const float* __restrict__ x,
                                             const float* __restrict__ att_src,
                                             const float* __restrict__ att_dst) {
    extern __shared__ char smem[];
    u32*   s_wf = (u32*)(smem + SOFF_WFRAG);     // hi; lo at +8192 u32
    u32*   s_xh = (u32*)(smem + SOFF_XH);        // [64 kp][XP_PITCH]
    u32*   s_xl = (u32*)(smem + SOFF_XL);
    float* s_o  = (float*)(smem + SOFF_OUT);     // [128 n][OUT_PITCH]

    const int tid  = threadIdx.x;
    const int wid  = tid >> 5;
    const int lane = tid & 31;
    const int b    = blockIdx.y;
    const int m0   = blockIdx.x * 128;           // node base
    const float* xb = x + (size_t)b * CCH * NNODES + m0;

    // ---- copy pre-baked W fragments (64 KB, coalesced) ----
    {
        float4* dst = (float4*)s_wf;
        const float4* src = (const float4*)g_Wfrag;
#pragma unroll
        for (int i = 0; i < 16; ++i) dst[tid + 256 * i] = src[tid + 256 * i];
    }
    // ---- load x tile, split hi/lo, pack k-pairs ----
    for (int t = tid; t < 64 * 128; t += 256) {
        const int kp = t >> 7;
        const int n  = t & 127;
        const float a0 = xb[(size_t)(2 * kp) * NNODES + n];
        const float a1 = xb[(size_t)(2 * kp + 1) * NNODES + n];
        const __nv_bfloat16 h0 = __float2bfloat16(a0);
        const __nv_bfloat16 h1 = __float2bfloat16(a1);
        const __nv_bfloat16 l0 = __float2bfloat16(a0 - __bfloat162float(h0));
        const __nv_bfloat16 l1 = __float2bfloat16(a1 - __bfloat162float(h1));
        s_xh[kp * XP_PITCH + n] = (u32)__bfloat16_as_ushort(h0) | ((u32)__bfloat16_as_ushort(h1) << 16);
        s_xl[kp * XP_PITCH + n] = (u32)__bfloat16_as_ushort(l0) | ((u32)__bfloat16_as_ushort(l1) << 16);
    }
    __syncthreads();

    // ---- mma mainloop: warp owns 16 nodes (2 n-groups of 8) x all 128 c_out ----
    const int n0 = wid * 16;
    float acc[8][2][4];
#pragma unroll
    for (int mt = 0; mt < 8; ++mt)
#pragma unroll
        for (int gg = 0; gg < 2; ++gg)
#pragma unroll
            for (int r = 0; r < 4; ++r) acc[mt][gg][r] = 0.f;

    const int nA  = n0 + (lane >> 2);            // B-frag col for group 0
#pragma unroll
    for (int kt = 0; kt < 8; ++kt) {
        const int kp0 = kt * 8 + (lane & 3);
        u32 bh[2][2], bl[2][2];
#pragma unroll
        for (int gg = 0; gg < 2; ++gg) {
            const int nn = nA + gg * 8;
            bh[gg][0] = s_xh[kp0 * XP_PITCH + nn];
            bh[gg][1] = s_xh[(kp0 + 4) * XP_PITCH + nn];
            bl[gg][0] = s_xl[kp0 * XP_PITCH + nn];
            bl[gg][1] = s_xl[(kp0 + 4) * XP_PITCH + nn];
        }
#pragma unroll
        for (int mt = 0; mt < 8; ++mt) {
            const u32 fbase = ((u32)(kt * 8 + mt) * 32 + lane) * 4;
            u32 ah[4], al[4];
            *(uint4*)ah = *(const uint4*)&s_wf[fbase];
            *(uint4*)al = *(const uint4*)&s_wf[8192 + fbase];
#pragma unroll
            for (int gg = 0; gg < 2; ++gg) {
                mma_bf16(acc[mt][gg], ah, bh[gg]);   // hi*hi
                mma_bf16(acc[mt][gg], ah, bl[gg]);   // lo_x * hi_w   (b is x)
                mma_bf16(acc[mt][gg], al, bh[gg]);   // hi_x * lo_w
            }
        }
    }
    __syncthreads();   // all warps done reading Xp before s_o overwrites it

    // ---- scatter fragments to s_o[n][c]  (bank: 4n+c -> all 32 distinct) ----
#pragma unroll
    for (int mt = 0; mt < 8; ++mt) {
        const int c = mt * 16 + (lane >> 2);
#pragma unroll
        for (int gg = 0; gg < 2; ++gg) {
            const int n = n0 + gg * 8 + (lane & 3) * 2;
            s_o[n * OUT_PITCH + c]           = acc[mt][gg][0];
            s_o[(n + 1) * OUT_PITCH + c]     = acc[mt][gg][1];
            s_o[n * OUT_PITCH + c + 8]       = acc[mt][gg][2];
            s_o[(n + 1) * OUT_PITCH + c + 8] = acc[mt][gg][3];
        }
    }
    __syncthreads();

    // ---- epilogue: store xp [n][c] + fused attention logits ----
    const int cch = lane * 4;
    const float4 asv = *(const float4*)&att_src[cch];
    const float4 adv = *(const float4*)&att_dst[cch];
#pragma unroll 1
    for (int i = 0; i < 16; ++i) {
        const int nl = wid * 16 + i;
        const float4 v = *(const float4*)&s_o[nl * OUT_PITCH + cch];
        *(float4*)&g_xp[((size_t)b * NNODES + m0 + nl) * CCH + cch] = v;

        float s = v.x * asv.x + v.y * asv.y + v.z * asv.z + v.w * asv.w;
        float d = v.x * adv.x + v.y * adv.y + v.z * adv.z + v.w * adv.w;
        s += __shfl_xor_sync(0xffffffffu, s, 1);
        s += __shfl_xor_sync(0xffffffffu, s, 2);
        d += __shfl_xor_sync(0xffffffffu, d, 1);
        d += __shfl_xor_sync(0xffffffffu, d, 2);
        if ((lane & 3) == 0) {
            g_asrc[((size_t)b * NNODES + m0 + nl) * HEADS + (lane >> 2)] = s;
            g_adst[((size_t)b * NNODES + m0 + nl) * HEADS + (lane >> 2)] = d;
        }
    }
}

// ---------------- Kernel C: softmax-stencil aggregate + bias + ELU + LN + transpose store ----------------
#define TR 8
#define TC_T 8
#define HC 10
#define HNODES (10 * 10)
#define TNODES (TR * TC_T)
#define OPITCH 132
#define AGG_THREADS 512

#define SMEM_AGG ((HNODES * 128 + HNODES * 8 + TNODES * 8 + TNODES * OPITCH) * 4)

__global__ __launch_bounds__(AGG_THREADS, 2) void agg_k(const float* __restrict__ bias,
                                                        const float* __restrict__ gamma,
                                                        const float* __restrict__ beta,
                                                        float* __restrict__ out) {
    extern __shared__ float sm[];
    float* s_xp  = sm;                          // [HNODES][128]
    float* s_as  = s_xp + HNODES * 128;         // [HNODES][8]
    float* s_ad  = s_as + HNODES * 8;           // [TNODES][8]
    float* s_out = s_ad + TNODES * 8;           // [TNODES][OPITCH]

    const int b  = blockIdx.z;
    const int r0 = blockIdx.y * TR;
    const int c0 = blockIdx.x * TC_T;
    const float* xpb = g_xp   + (size_t)b * NNODES * CCH;
    const float* asb = g_asrc + (size_t)b * NNODES * HEADS;
    const float* adb = g_adst + (size_t)b * NNODES * HEADS;

    for (int t = threadIdx.x; t < HNODES * 32; t += AGG_THREADS) {
        const int row = t >> 5;
        const int pos = (t & 31) << 2;
        const int hr = row / HC, hc = row - hr * HC;
        const int rg = r0 - 1 + hr, cg = c0 - 1 + hc;
        float4 v = {0.f, 0.f, 0.f, 0.f};
        if ((unsigned)rg < HH && (unsigned)cg < WWID)
            v = *(const float4*)&xpb[(size_t)(rg * WWID + cg) * CCH + pos];
        *(float4*)&s_xp[row * 128 + pos] = v;
    }
    for (int t = threadIdx.x; t < HNODES * 8; t += AGG_THREADS) {
        const int row = t >> 3;
        const int hr = row / HC, hc = row - hr * HC;
        const int rg = r0 - 1 + hr, cg = c0 - 1 + hc;
        float v = 0.f;
        if ((unsigned)rg < HH && (unsigned)cg < WWID)
            v = asb[(rg * WWID + cg) * HEADS + (t & 7)];
        s_as[t] = v;
    }
    for (int t = threadIdx.x; t < TNODES * 8; t += AGG_THREADS) {
        const int node = t >> 3;
        const int lr = node >> 3, lc = node & 7;
        s_ad[t] = adb[((r0 + lr) * WWID + c0 + lc) * HEADS + (t & 7)];
    }
    __syncthreads();

    const int warp = threadIdx.x >> 5;
    const int lane = threadIdx.x & 31;
    const int h    = lane >> 2;
    const int cch  = lane << 2;

    const float4 bv = *(const float4*)&bias[cch];
    const float4 gv = *(const float4*)&gamma[cch];
    const float4 be = *(const float4*)&beta[cch];

#pragma unroll 1
    for (int i = 0; i < 4; ++i) {
        const int nl = warp * 4 + i;
        const int lr = nl >> 3, lc = nl & 7;
        const int rg = r0 + lr, cg = c0 + lc;

        const float adst = s_ad[nl * 8 + h];

        float e[9];
        float M = -1e30f;
#pragma unroll
        for (int m = 0; m < 9; ++m) {
            const int dr = m / 3 - 1, dc = m % 3 - 1;
            const int hrow = (lr + 1 + dr) * HC + (lc + 1 + dc);
            float sc = s_as[hrow * 8 + h] + adst;
            sc = sc > 0.f ? sc : 0.2f * sc;
            const bool ok = ((unsigned)(rg + dr) < HH) && ((unsigned)(cg + dc) < WWID);
            e[m] = ok ? sc : -1e30f;
            M = fmaxf(M, e[m]);
        }
        float den = 0.f;
#pragma unroll
        for (int m = 0; m < 9; ++m) { e[m] = __expf(e[m] - M); den += e[m]; }
        den += e[4];
        const float inv = __fdividef(1.0f, den);

        float a0 = 0.f, a1 = 0.f, a2 = 0.f, a3 = 0.f;
#pragma unroll
        for (int m = 0; m < 9; ++m) {
            float w = e[m] * inv;
            if (m == 4) w += w;
            const int dr = m / 3 - 1, dc = m % 3 - 1;
            const int hrow = (lr + 1 + dr) * HC + (lc + 1 + dc);
            const float4 v = *(const float4*)&s_xp[hrow * 128 + cch];
            a0 = fmaf(w, v.x, a0);
            a1 = fmaf(w, v.y, a1);
            a2 = fmaf(w, v.z, a2);
            a3 = fmaf(w, v.w, a3);
        }
        float o0 = a0 + bv.x, o1 = a1 + bv.y, o2 = a2 + bv.z, o3 = a3 + bv.w;
        o0 = o0 > 0.f ? o0 : (__expf(o0) - 1.f);
        o1 = o1 > 0.f ? o1 : (__expf(o1) - 1.f);
        o2 = o2 > 0.f ? o2 : (__expf(o2) - 1.f);
        o3 = o3 > 0.f ? o3 : (__expf(o3) - 1.f);
        float sum = o0 + o1 + o2 + o3;
        float sq  = o0 * o0 + o1 * o1 + o2 * o2 + o3 * o3;
#pragma unroll
        for (int off = 16; off; off >>= 1) {
            sum += __shfl_xor_sync(0xffffffffu, sum, off);
            sq  += __shfl_xor_sync(0xffffffffu, sq,  off);
        }
        const float mu   = sum * 0.0078125f;
        const float var  = sq * 0.0078125f - mu * mu;
        const float rstd = rsqrtf(var + 1e-5f);

        float4 y;
        y.x = (o0 - mu) * rstd * gv.x + be.x;
        y.y = (o1 - mu) * rstd * gv.y + be.y;
        y.z = (o2 - mu) * rstd * gv.z + be.z;
        y.w = (o3 - mu) * rstd * gv.w + be.w;
        *(float4*)&s_out[nl * OPITCH + cch] = y;
    }
    __syncthreads();

    float* ob = out + (size_t)b * CCH * NNODES;
    for (int t = threadIdx.x; t < CCH * TNODES; t += AGG_THREADS) {
        const int c = t >> 6;
        const int node = t & 63;
        const int lr = node >> 3, lc = node & 7;
        ob[(size_t)c * NNODES + (r0 + lr) * WWID + c0 + lc] = s_out[node * OPITCH + c];
    }
}

// ---------------- launch ----------------
extern "C" void kernel_launch(void* const* d_in, const int* in_sizes, int n_in,
                              void* d_out, int out_size) {
    const float* x       = (const float*)d_in[0];
    const float* Wl      = (const float*)d_in[1];
    const float* att_src = (const float*)d_in[2];
    const float* att_dst = (const float*)d_in[3];
    const float* bias    = (const float*)d_in[4];
    const float* gamma   = (const float*)d_in[5];
    const float* beta    = (const float*)d_in[6];
    float* out = (float*)d_out;

    cudaFuncSetAttribute(mma_k, cudaFuncAttributeMaxDynamicSharedMemorySize, SMEM_MMA);
    cudaFuncSetAttribute(agg_k, cudaFuncAttributeMaxDynamicSharedMemorySize, SMEM_AGG);

    bprep_k<<<8, 256>>>(Wl);
    mma_k<<<dim3(NNODES / 128, BATCH), 256, SMEM_MMA>>>(x, att_src, att_dst);
    agg_k<<<dim3(WWID / TC_T, HH / TR, BATCH), AGG_THREADS, SMEM_AGG>>>(bias, gamma, beta, out);
}

// round 14
// speedup vs baseline: 1.9293x; 1.2059x over previous
#include <cuda_runtime.h>
#include <cuda_bf16.h>
#include <cstdint>

#define BATCH 4
#define CCH   128
#define HH    128
#define WWID  128
#define NNODES (HH*WWID)
#define HEADS 8

typedef unsigned int u32;

// ---------------- scratch (static device globals; no allocation) ----------------
__device__ float g_xp  [BATCH * NNODES * CCH];    // [B][N][C] projected features
__device__ float g_asrc[BATCH * NNODES * HEADS];
__device__ float g_adst[BATCH * NNODES * HEADS];
// Pre-baked W fragments for mma.sync m16n8k16 (A-operand = W^T, row-major [m=c_out][k=c_in])
// layout: [hi(0)/lo(1)][tile = kt*8+mt][lane 0..31][reg 0..3]  (u32 bf16x2)
__device__ u32 g_Wfrag[2 * 64 * 32 * 4];

// ---------------- mma.sync bf16 (sm_80+ path; compiles under compute_103) ----------------
__device__ __forceinline__ void mma_bf16(float* c, const u32* a, const u32* b) {
    asm volatile("mma.sync.aligned.m16n8k16.row.col.f32.bf16.bf16.f32 "
                 "{%0,%1,%2,%3}, {%4,%5,%6,%7}, {%8,%9}, {%0,%1,%2,%3};"
                 : "+f"(c[0]), "+f"(c[1]), "+f"(c[2]), "+f"(c[3])
                 : "r"(a[0]), "r"(a[1]), "r"(a[2]), "r"(a[3]),
                   "r"(b[0]), "r"(b[1]));
}

// ---------------- Kernel P: bake W^T hi/lo mma fragments ----------------
// A[m][k] = Wl[k*128 + m].  m16n8k16 A-frag: a0:(m=l/4, k=2(l%4)+{0,1}),
// a1:(m+8, k), a2:(m, k+8), a3:(m+8, k+8); bf16x2 low half = even k.
__global__ __launch_bounds__(256) void bprep_k(const float* __restrict__ Wl) {
    const int g = blockIdx.x * 256 + threadIdx.x;    // 0..8191 = tile*32*4 + lane*4 + r
    const int r  = g & 3;
    const int l  = (g >> 2) & 31;
    const int mt = (g >> 7) & 7;
    const int kt = g >> 10;
    const int m = mt * 16 + (l >> 2) + (r & 1) * 8;
    const int k = kt * 16 + (l & 3) * 2 + (r >> 1) * 8;
    const float v0 = Wl[k * CCH + m];
    const float v1 = Wl[(k + 1) * CCH + m];
    const __nv_bfloat16 h0 = __float2bfloat16(v0);
    const __nv_bfloat16 h1 = __float2bfloat16(v1);
    const __nv_bfloat16 l0 = __float2bfloat16(v0 - __bfloat162float(h0));
    const __nv_bfloat16 l1 = __float2bfloat16(v1 - __bfloat162float(h1));
    g_Wfrag[g]        = (u32)__bfloat16_as_ushort(h0) | ((u32)__bfloat16_as_ushort(h1) << 16);
    g_Wfrag[8192 + g] = (u32)__bfloat16_as_ushort(l0) | ((u32)__bfloat16_as_ushort(l1) << 16);
}

// ---------------- Kernel A: bf16x3 HMMA GEMM (C^T form) + fused attention logits ----
// D[c_out][node] = W^T @ x_tile.  B-operand = x in native [k][n] layout (no transpose).
// W fragments read straight from GMEM (L2/L1-resident 64KB) -> SMEM 68KB -> 2 CTAs/SM.
#define XP_PITCH 136                       // u32 words per kp-row: 136%32=8 -> conflict-free B frags
#define SOFF_XH    0                       // 64*136*4 = 34816 B
#define SOFF_XL    34816
#define SOFF_OUT   0                       // reuse Xp region after mma (67584 <= 69632)
#define OUT_PITCH  132                     // floats; 132%32=4 -> conflict-free frag stores
#define SMEM_MMA   (2 * 34816)

__global__ __launch_bounds__(256, 2) void mma_k(const float* __restrict__ x,
                                                const float* __restrict__ att_src,
                                                const float* __restrict__ att_dst) {
    extern __shared__ char smem[];
    u32*   s_xh = (u32*)(smem + SOFF_XH);        // [64 kp][XP_PITCH]
    u32*   s_xl = (u32*)(smem + SOFF_XL);
    float* s_o  = (float*)(smem + SOFF_OUT);     // [128 n][OUT_PITCH]

    const int tid  = threadIdx.x;
    const int wid  = tid >> 5;
    const int lane = tid & 31;
    const int b    = blockIdx.y;
    const int m0   = blockIdx.x * 128;           // node base
    const float* xb = x + (size_t)b * CCH * NNODES + m0;

    // ---- load x tile, split hi/lo, pack k-pairs ----
    for (int t = tid; t < 64 * 128; t += 256) {
        const int kp = t >> 7;
        const int n  = t & 127;
        const float a0 = xb[(size_t)(2 * kp) * NNODES + n];
        const float a1 = xb[(size_t)(2 * kp + 1) * NNODES + n];
        const __nv_bfloat16 h0 = __float2bfloat16(a0);
        const __nv_bfloat16 h1 = __float2bfloat16(a1);
        const __nv_bfloat16 l0 = __float2bfloat16(a0 - __bfloat162float(h0));
        const __nv_bfloat16 l1 = __float2bfloat16(a1 - __bfloat162float(h1));
        s_xh[kp * XP_PITCH + n] = (u32)__bfloat16_as_ushort(h0) | ((u32)__bfloat16_as_ushort(h1) << 16);
        s_xl[kp * XP_PITCH + n] = (u32)__bfloat16_as_ushort(l0) | ((u32)__bfloat16_as_ushort(l1) << 16);
    }
    __syncthreads();

    // ---- mma mainloop: warp owns 16 nodes (2 n-groups of 8) x all 128 c_out ----
    const int n0 = wid * 16;
    float acc[8][2][4];
#pragma unroll
    for (int mt = 0; mt < 8; ++mt)
#pragma unroll
        for (int gg = 0; gg < 2; ++gg)
#pragma unroll
            for (int r = 0; r < 4; ++r) acc[mt][gg][r] = 0.f;

    const int nA  = n0 + (lane >> 2);            // B-frag col for group 0
#pragma unroll
    for (int kt = 0; kt < 8; ++kt) {
        const int kp0 = kt * 8 + (lane & 3);
        u32 bh[2][2], bl[2][2];
#pragma unroll
        for (int gg = 0; gg < 2; ++gg) {
            const int nn = nA + gg * 8;
            bh[gg][0] = s_xh[kp0 * XP_PITCH + nn];
            bh[gg][1] = s_xh[(kp0 + 4) * XP_PITCH + nn];
            bl[gg][0] = s_xl[kp0 * XP_PITCH + nn];
            bl[gg][1] = s_xl[(kp0 + 4) * XP_PITCH + nn];
        }
#pragma unroll
        for (int mt = 0; mt < 8; ++mt) {
            const u32 fbase = ((u32)(kt * 8 + mt) * 32 + lane) * 4;
            u32 ah[4], al[4];
            *(uint4*)ah = __ldg((const uint4*)&g_Wfrag[fbase]);
            *(uint4*)al = __ldg((const uint4*)&g_Wfrag[8192 + fbase]);
#pragma unroll
            for (int gg = 0; gg < 2; ++gg) {
                mma_bf16(acc[mt][gg], ah, bh[gg]);   // hi*hi
                mma_bf16(acc[mt][gg], ah, bl[gg]);   // hi_w * lo_x
                mma_bf16(acc[mt][gg], al, bh[gg]);   // lo_w * hi_x
            }
        }
    }
    __syncthreads();   // all warps done reading Xp before s_o overwrites it

    // ---- scatter fragments to s_o[n][c]  (bank: 4n+c -> all 32 distinct) ----
#pragma unroll
    for (int mt = 0; mt < 8; ++mt) {
        const int c = mt * 16 + (lane >> 2);
#pragma unroll
        for (int gg = 0; gg < 2; ++gg) {
            const int n = n0 + gg * 8 + (lane & 3) * 2;
            s_o[n * OUT_PITCH + c]           = acc[mt][gg][0];
            s_o[(n + 1) * OUT_PITCH + c]     = acc[mt][gg][1];
            s_o[n * OUT_PITCH + c + 8]       = acc[mt][gg][2];
            s_o[(n + 1) * OUT_PITCH + c + 8] = acc[mt][gg][3];
        }
    }
    __syncthreads();

    // ---- epilogue: store xp [n][c] + fused attention logits ----
    const int cch = lane * 4;
    const float4 asv = *(const float4*)&att_src[cch];
    const float4 adv = *(const float4*)&att_dst[cch];
#pragma unroll 1
    for (int i = 0; i < 16; ++i) {
        const int nl = wid * 16 + i;
        const float4 v = *(const float4*)&s_o[nl * OUT_PITCH + cch];
        *(float4*)&g_xp[((size_t)b * NNODES + m0 + nl) * CCH + cch] = v;

        float s = v.x * asv.x + v.y * asv.y + v.z * asv.z + v.w * asv.w;
        float d = v.x * adv.x + v.y * adv.y + v.z * adv.z + v.w * adv.w;
        s += __shfl_xor_sync(0xffffffffu, s, 1);
        s += __shfl_xor_sync(0xffffffffu, s, 2);
        d += __shfl_xor_sync(0xffffffffu, d, 1);
        d += __shfl_xor_sync(0xffffffffu, d, 2);
        if ((lane & 3) == 0) {
            g_asrc[((size_t)b * NNODES + m0 + nl) * HEADS + (lane >> 2)] = s;
            g_adst[((size_t)b * NNODES + m0 + nl) * HEADS + (lane >> 2)] = d;
        }
    }
}

// ---------------- Kernel C: softmax-stencil aggregate + bias + ELU + LN + transpose store ----------------
#define TR 8
#define TC_T 8
#define HC 10
#define HNODES (10 * 10)
#define TNODES (TR * TC_T)
#define OPITCH 132
#define AGG_THREADS 512

#define SMEM_AGG ((HNODES * 128 + HNODES * 8 + TNODES * 8 + TNODES * OPITCH) * 4)

__global__ __launch_bounds__(AGG_THREADS, 2) void agg_k(const float* __restrict__ bias,
                                                        const float* __restrict__ gamma,
                                                        const float* __restrict__ beta,
                                                        float* __restrict__ out) {
    extern __shared__ float sm[];
    float* s_xp  = sm;                          // [HNODES][128]
    float* s_as  = s_xp + HNODES * 128;         // [HNODES][8]
    float* s_ad  = s_as + HNODES * 8;           // [TNODES][8]
    float* s_out = s_ad + TNODES * 8;           // [TNODES][OPITCH]

    const int b  = blockIdx.z;
    const int r0 = blockIdx.y * TR;
    const int c0 = blockIdx.x * TC_T;
    const float* xpb = g_xp   + (size_t)b * NNODES * CCH;
    const float* asb = g_asrc + (size_t)b * NNODES * HEADS;
    const float* adb = g_adst + (size_t)b * NNODES * HEADS;

    for (int t = threadIdx.x; t < HNODES * 32; t += AGG_THREADS) {
        const int row = t >> 5;
        const int pos = (t & 31) << 2;
        const int hr = row / HC, hc = row - hr * HC;
        const int rg = r0 - 1 + hr, cg = c0 - 1 + hc;
        float4 v = {0.f, 0.f, 0.f, 0.f};
        if ((unsigned)rg < HH && (unsigned)cg < WWID)
            v = *(const float4*)&xpb[(size_t)(rg * WWID + cg) * CCH + pos];
        *(float4*)&s_xp[row * 128 + pos] = v;
    }
    for (int t = threadIdx.x; t < HNODES * 8; t += AGG_THREADS) {
        const int row = t >> 3;
        const int hr = row / HC, hc = row - hr * HC;
        const int rg = r0 - 1 + hr, cg = c0 - 1 + hc;
        float v = 0.f;
        if ((unsigned)rg < HH && (unsigned)cg < WWID)
            v = asb[(rg * WWID + cg) * HEADS + (t & 7)];
        s_as[t] = v;
    }
    for (int t = threadIdx.x; t < TNODES * 8; t += AGG_THREADS) {
        const int node = t >> 3;
        const int lr = node >> 3, lc = node & 7;
        s_ad[t] = adb[((r0 + lr) * WWID + c0 + lc) * HEADS + (t & 7)];
    }
    __syncthreads();

    const int warp = threadIdx.x >> 5;
    const int lane = threadIdx.x & 31;
    const int h    = lane >> 2;
    const int cch  = lane << 2;

    const float4 bv = *(const float4*)&bias[cch];
    const float4 gv = *(const float4*)&gamma[cch];
    const float4 be = *(const float4*)&beta[cch];

#pragma unroll 1
    for (int i = 0; i < 4; ++i) {
        const int nl = warp * 4 + i;
        const int lr = nl >> 3, lc = nl & 7;
        const int rg = r0 + lr, cg = c0 + lc;

        const float adst = s_ad[nl * 8 + h];

        float e[9];
        float M = -1e30f;
#pragma unroll
        for (int m = 0; m < 9; ++m) {
            const int dr = m / 3 - 1, dc = m % 3 - 1;
            const int hrow = (lr + 1 + dr) * HC + (lc + 1 + dc);
            float sc = s_as[hrow * 8 + h] + adst;
            sc = sc > 0.f ? sc : 0.2f * sc;
            const bool ok = ((unsigned)(rg + dr) < HH) && ((unsigned)(cg + dc) < WWID);
            e[m] = ok ? sc : -1e30f;
            M = fmaxf(M, e[m]);
        }
        float den = 0.f;
#pragma unroll
        for (int m = 0; m < 9; ++m) { e[m] = __expf(e[m] - M); den += e[m]; }
        den += e[4];
        const float inv = __fdividef(1.0f, den);

        float a0 = 0.f, a1 = 0.f, a2 = 0.f, a3 = 0.f;
#pragma unroll
        for (int m = 0; m < 9; ++m) {
            float w = e[m] * inv;
            if (m == 4) w += w;
            const int dr = m / 3 - 1, dc = m % 3 - 1;
            const int hrow = (lr + 1 + dr) * HC + (lc + 1 + dc);
            const float4 v = *(const float4*)&s_xp[hrow * 128 + cch];
            a0 = fmaf(w, v.x, a0);
            a1 = fmaf(w, v.y, a1);
            a2 = fmaf(w, v.z, a2);
            a3 = fmaf(w, v.w, a3);
        }
        float o0 = a0 + bv.x, o1 = a1 + bv.y, o2 = a2 + bv.z, o3 = a3 + bv.w;
        o0 = o0 > 0.f ? o0 : (__expf(o0) - 1.f);
        o1 = o1 > 0.f ? o1 : (__expf(o1) - 1.f);
        o2 = o2 > 0.f ? o2 : (__expf(o2) - 1.f);
        o3 = o3 > 0.f ? o3 : (__expf(o3) - 1.f);
        float sum = o0 + o1 + o2 + o3;
        float sq  = o0 * o0 + o1 * o1 + o2 * o2 + o3 * o3;
#pragma unroll
        for (int off = 16; off; off >>= 1) {
            sum += __shfl_xor_sync(0xffffffffu, sum, off);
            sq  += __shfl_xor_sync(0xffffffffu, sq,  off);
        }
        const float mu   = sum * 0.0078125f;
        const float var  = sq * 0.0078125f - mu * mu;
        const float rstd = rsqrtf(var + 1e-5f);

        float4 y;
        y.x = (o0 - mu) * rstd * gv.x + be.x;
        y.y = (o1 - mu) * rstd * gv.y + be.y;
        y.z = (o2 - mu) * rstd * gv.z + be.z;
        y.w = (o3 - mu) * rstd * gv.w + be.w;
        *(float4*)&s_out[nl * OPITCH + cch] = y;
    }
    __syncthreads();

    float* ob = out + (size_t)b * CCH * NNODES;
    for (int t = threadIdx.x; t < CCH * TNODES; t += AGG_THREADS) {
        const int c = t >> 6;
        const int node = t & 63;
        const int lr = node >> 3, lc = node & 7;
        ob[(size_t)c * NNODES + (r0 + lr) * WWID + c0 + lc] = s_out[node * OPITCH + c];
    }
}

// ---------------- launch ----------------
extern "C" void kernel_launch(void* const* d_in, const int* in_sizes, int n_in,
                              void* d_out, int out_size) {
    const float* x       = (const float*)d_in[0];
    const float* Wl      = (const float*)d_in[1];
    const float* att_src = (const float*)d_in[2];
    const float* att_dst = (const float*)d_in[3];
    const float* bias    = (const float*)d_in[4];
    const float* gamma   = (const float*)d_in[5];
    const float* beta    = (const float*)d_in[6];
    float* out = (float*)d_out;

    cudaFuncSetAttribute(mma_k, cudaFuncAttributeMaxDynamicSharedMemorySize, SMEM_MMA);
    cudaFuncSetAttribute(agg_k, cudaFuncAttributeMaxDynamicSharedMemorySize, SMEM_AGG);

    bprep_k<<<32, 256>>>(Wl);
    mma_k<<<dim3(NNODES / 128, BATCH), 256, SMEM_MMA>>>(x, att_src, att_dst);
    agg_k<<<dim3(WWID / TC_T, HH / TR, BATCH), AGG_THREADS, SMEM_AGG>>>(bias, gamma, beta, out);
}

// round 15
// speedup vs baseline: 2.0807x; 1.0785x over previous
#include <cuda_runtime.h>
#include <cuda_bf16.h>
#include <cstdint>

#define BATCH 4
#define CCH   128
#define HH    128
#define WWID  128
#define NNODES (HH*WWID)
#define HEADS 8

typedef unsigned int u32;
typedef unsigned long long u64;

// ---------------- scratch (static device globals; no allocation) ----------------
__device__ float g_xp  [BATCH * NNODES * CCH];    // [B][N][C] projected features
__device__ float g_asrc[BATCH * NNODES * HEADS];
__device__ float g_adst[BATCH * NNODES * HEADS];
// Pre-baked W fragments for mma.sync m16n8k16 (A-operand = W^T, row-major [m=c_out][k=c_in])
__device__ u32 g_Wfrag[2 * 64 * 32 * 4];

// ---------------- packed f32x2 helpers ----------------
__device__ __forceinline__ u64 pack2_dup(float x) {
    u64 r; unsigned xi = __float_as_uint(x);
    asm("mov.b64 %0, {%1, %1};" : "=l"(r) : "r"(xi));
    return r;
}
__device__ __forceinline__ void fma2(u64& d, u64 a, u64 b) {
    asm("fma.rn.f32x2 %0, %1, %2, %0;" : "+l"(d) : "l"(a), "l"(b));
}
__device__ __forceinline__ float2 unpack2(u64 v) {
    unsigned lo, hi;
    asm("mov.b64 {%0, %1}, %2;" : "=r"(lo), "=r"(hi) : "l"(v));
    float2 f; f.x = __uint_as_float(lo); f.y = __uint_as_float(hi);
    return f;
}

// ---------------- mma.sync bf16 ----------------
__device__ __forceinline__ void mma_bf16(float* c, const u32* a, const u32* b) {
    asm volatile("mma.sync.aligned.m16n8k16.row.col.f32.bf16.bf16.f32 "
                 "{%0,%1,%2,%3}, {%4,%5,%6,%7}, {%8,%9}, {%0,%1,%2,%3};"
                 : "+f"(c[0]), "+f"(c[1]), "+f"(c[2]), "+f"(c[3])
                 : "r"(a[0]), "r"(a[1]), "r"(a[2]), "r"(a[3]),
                   "r"(b[0]), "r"(b[1]));
}

// ---------------- Kernel P: bake W^T hi/lo mma fragments ----------------
__global__ __launch_bounds__(256) void bprep_k(const float* __restrict__ Wl) {
    const int g = blockIdx.x * 256 + threadIdx.x;    // 0..8191
    const int r  = g & 3;
    const int l  = (g >> 2) & 31;
    const int mt = (g >> 7) & 7;
    const int kt = g >> 10;
    const int m = mt * 16 + (l >> 2) + (r & 1) * 8;
    const int k = kt * 16 + (l & 3) * 2 + (r >> 1) * 8;
    const float v0 = Wl[k * CCH + m];
    const float v1 = Wl[(k + 1) * CCH + m];
    u32 hp; asm("cvt.rn.bf16x2.f32 %0, %1, %2;" : "=r"(hp) : "f"(v1), "f"(v0));
    const float h0 = __uint_as_float(hp << 16);
    const float h1 = __uint_as_float(hp & 0xffff0000u);
    u32 lp; asm("cvt.rn.bf16x2.f32 %0, %1, %2;" : "=r"(lp) : "f"(v1 - h1), "f"(v0 - h0));
    g_Wfrag[g]        = hp;
    g_Wfrag[8192 + g] = lp;
}

// ---------------- Kernel A: bf16x3 HMMA GEMM (C^T form) + fused attention logits ----
#define XP_PITCH 136
#define SOFF_XH    0
#define SOFF_XL    34816
#define SOFF_OUT   0
#define OUT_PITCH  132
#define SMEM_MMA   (2 * 34816)

__global__ __launch_bounds__(256, 2) void mma_k(const float* __restrict__ x,
                                                const float* __restrict__ att_src,
                                                const float* __restrict__ att_dst) {
    extern __shared__ char smem[];
    u32*   s_xh = (u32*)(smem + SOFF_XH);        // [64 kp][XP_PITCH]
    u32*   s_xl = (u32*)(smem + SOFF_XL);
    float* s_o  = (float*)(smem + SOFF_OUT);     // [128 n][OUT_PITCH]

    const int tid  = threadIdx.x;
    const int wid  = tid >> 5;
    const int lane = tid & 31;
    const int b    = blockIdx.y;
    const int m0   = blockIdx.x * 128;           // node base
    const float* xb = x + (size_t)b * CCH * NNODES + m0;

    // ---- load x tile, split hi/lo via cvt.bf16x2, pack k-pairs ----
    for (int t = tid; t < 64 * 128; t += 256) {
        const int kp = t >> 7;
        const int n  = t & 127;
        const float a0 = xb[(size_t)(2 * kp) * NNODES + n];
        const float a1 = xb[(size_t)(2 * kp + 1) * NNODES + n];
        u32 hp; asm("cvt.rn.bf16x2.f32 %0, %1, %2;" : "=r"(hp) : "f"(a1), "f"(a0));
        const float h0 = __uint_as_float(hp << 16);
        const float h1 = __uint_as_float(hp & 0xffff0000u);
        u32 lp; asm("cvt.rn.bf16x2.f32 %0, %1, %2;" : "=r"(lp) : "f"(a1 - h1), "f"(a0 - h0));
        s_xh[kp * XP_PITCH + n] = hp;
        s_xl[kp * XP_PITCH + n] = lp;
    }
    __syncthreads();

    // ---- mma mainloop: warp owns 16 nodes (2 n-groups of 8) x all 128 c_out ----
    const int n0 = wid * 16;
    float acc[8][2][4];
#pragma unroll
    for (int mt = 0; mt < 8; ++mt)
#pragma unroll
        for (int gg = 0; gg < 2; ++gg)
#pragma unroll
            for (int r = 0; r < 4; ++r) acc[mt][gg][r] = 0.f;

    const int nA  = n0 + (lane >> 2);
#pragma unroll
    for (int kt = 0; kt < 8; ++kt) {
        const int kp0 = kt * 8 + (lane & 3);
        u32 bh[2][2], bl[2][2];
#pragma unroll
        for (int gg = 0; gg < 2; ++gg) {
            const int nn = nA + gg * 8;
            bh[gg][0] = s_xh[kp0 * XP_PITCH + nn];
            bh[gg][1] = s_xh[(kp0 + 4) * XP_PITCH + nn];
            bl[gg][0] = s_xl[kp0 * XP_PITCH + nn];
            bl[gg][1] = s_xl[(kp0 + 4) * XP_PITCH + nn];
        }
#pragma unroll
        for (int mt = 0; mt < 8; ++mt) {
            const u32 fbase = ((u32)(kt * 8 + mt) * 32 + lane) * 4;
            u32 ah[4], al[4];
            *(uint4*)ah = __ldg((const uint4*)&g_Wfrag[fbase]);
            *(uint4*)al = __ldg((const uint4*)&g_Wfrag[8192 + fbase]);
#pragma unroll
            for (int gg = 0; gg < 2; ++gg) {
                mma_bf16(acc[mt][gg], ah, bh[gg]);   // hi*hi
                mma_bf16(acc[mt][gg], ah, bl[gg]);   // hi_w * lo_x
                mma_bf16(acc[mt][gg], al, bh[gg]);   // lo_w * hi_x
            }
        }
    }
    __syncthreads();   // all warps done reading Xp before s_o overwrites it

    // ---- scatter fragments to s_o[n][c] (warp-private rows; no sync needed after) ----
#pragma unroll
    for (int mt = 0; mt < 8; ++mt) {
        const int c = mt * 16 + (lane >> 2);
#pragma unroll
        for (int gg = 0; gg < 2; ++gg) {
            const int n = n0 + gg * 8 + (lane & 3) * 2;
            s_o[n * OUT_PITCH + c]           = acc[mt][gg][0];
            s_o[(n + 1) * OUT_PITCH + c]     = acc[mt][gg][1];
            s_o[n * OUT_PITCH + c + 8]       = acc[mt][gg][2];
            s_o[(n + 1) * OUT_PITCH + c + 8] = acc[mt][gg][3];
        }
    }

    // ---- epilogue: store xp [n][c] + fused attention logits (own rows only) ----
    const int cch = lane * 4;
    const float4 asv = *(const float4*)&att_src[cch];
    const float4 adv = *(const float4*)&att_dst[cch];
#pragma unroll 4
    for (int i = 0; i < 16; ++i) {
        const int nl = wid * 16 + i;
        const float4 v = *(const float4*)&s_o[nl * OUT_PITCH + cch];
        *(float4*)&g_xp[((size_t)b * NNODES + m0 + nl) * CCH + cch] = v;

        float s = v.x * asv.x + v.y * asv.y + v.z * asv.z + v.w * asv.w;
        float d = v.x * adv.x + v.y * adv.y + v.z * adv.z + v.w * adv.w;
        s += __shfl_xor_sync(0xffffffffu, s, 1);
        s += __shfl_xor_sync(0xffffffffu, s, 2);
        d += __shfl_xor_sync(0xffffffffu, d, 1);
        d += __shfl_xor_sync(0xffffffffu, d, 2);
        if ((lane & 3) == 0) {
            g_asrc[((size_t)b * NNODES + m0 + nl) * HEADS + (lane >> 2)] = s;
            g_adst[((size_t)b * NNODES + m0 + nl) * HEADS + (lane >> 2)] = d;
        }
    }
}

// ---------------- Kernel C: softmax-stencil aggregate + bias + ELU + LN + transpose store ----------------
#define TR 8
#define TC_T 8
#define HC 10
#define HNODES (10 * 10)
#define TNODES (TR * TC_T)
#define OPITCH 132
#define AGG_THREADS 512

#define SMEM_AGG ((HNODES * 128 + HNODES * 8 + TNODES * 8 + TNODES * OPITCH) * 4)

// Per-node body. MASK=true adds image-boundary validity masking.
template <bool MASK>
__device__ __forceinline__ void agg_node(
    const int nl, const int lr, const int lc, const int rg, const int cg,
    const float* __restrict__ s_as, const float* __restrict__ s_ad,
    const float* __restrict__ s_xp, float* __restrict__ s_out,
    const int h, const int cch,
    const float4 bv, const float4 gv, const float4 be)
{
    const float adst = s_ad[nl * 8 + h];

    float e[9];
    float M = -1e30f;
#pragma unroll
    for (int m = 0; m < 9; ++m) {
        const int dr = m / 3 - 1, dc = m % 3 - 1;
        const int hrow = (lr + 1 + dr) * HC + (lc + 1 + dc);
        float sc = s_as[hrow * 8 + h] + adst;
        sc = sc > 0.f ? sc : 0.2f * sc;                 // leaky_relu(0.2)
        if (MASK) {
            const bool ok = ((unsigned)(rg + dr) < HH) && ((unsigned)(cg + dc) < WWID);
            sc = ok ? sc : -1e30f;
        }
        e[m] = sc;
        M = fmaxf(M, sc);
    }
    float den = 0.f;
#pragma unroll
    for (int m = 0; m < 9; ++m) { e[m] = __expf(e[m] - M); den += e[m]; }
    den += e[4];                                        // duplicated self-loop
    const float inv = __fdividef(1.0f, den);

    // packed f32x2 aggregation (halves FMA issue count)
    u64 acc01 = 0ull, acc23 = 0ull;
#pragma unroll
    for (int m = 0; m < 9; ++m) {
        float w = e[m] * inv;
        if (m == 4) w += w;                             // self counted twice
        const int dr = m / 3 - 1, dc = m % 3 - 1;
        const int hrow = (lr + 1 + dr) * HC + (lc + 1 + dc);
        const ulonglong2 v = *(const ulonglong2*)&s_xp[hrow * 128 + cch];
        const u64 wd = pack2_dup(w);
        fma2(acc01, wd, v.x);
        fma2(acc23, wd, v.y);
    }
    const float2 p01 = unpack2(acc01);
    const float2 p23 = unpack2(acc23);

    // bias + ELU
    float o0 = p01.x + bv.x, o1 = p01.y + bv.y, o2 = p23.x + bv.z, o3 = p23.y + bv.w;
    o0 = o0 > 0.f ? o0 : (__expf(o0) - 1.f);
    o1 = o1 > 0.f ? o1 : (__expf(o1) - 1.f);
    o2 = o2 > 0.f ? o2 : (__expf(o2) - 1.f);
    o3 = o3 > 0.f ? o3 : (__expf(o3) - 1.f);
    // LayerNorm over 128 channels (warp allreduce)
    float sum = o0 + o1 + o2 + o3;
    float sq  = o0 * o0 + o1 * o1 + o2 * o2 + o3 * o3;
#pragma unroll
    for (int off = 16; off; off >>= 1) {
        sum += __shfl_xor_sync(0xffffffffu, sum, off);
        sq  += __shfl_xor_sync(0xffffffffu, sq,  off);
    }
    const float mu   = sum * 0.0078125f;
    const float var  = sq * 0.0078125f - mu * mu;
    const float rstd = rsqrtf(var + 1e-5f);

    float4 y;
    y.x = (o0 - mu) * rstd * gv.x + be.x;
    y.y = (o1 - mu) * rstd * gv.y + be.y;
    y.z = (o2 - mu) * rstd * gv.z + be.z;
    y.w = (o3 - mu) * rstd * gv.w + be.w;
    *(float4*)&s_out[nl * OPITCH + cch] = y;
}

__global__ __launch_bounds__(AGG_THREADS, 2) void agg_k(const float* __restrict__ bias,
                                                        const float* __restrict__ gamma,
                                                        const float* __restrict__ beta,
                                                        float* __restrict__ out) {
    extern __shared__ float sm[];
    float* s_xp  = sm;                          // [HNODES][128]
    float* s_as  = s_xp + HNODES * 128;         // [HNODES][8]
    float* s_ad  = s_as + HNODES * 8;           // [TNODES][8]
    float* s_out = s_ad + TNODES * 8;           // [TNODES][OPITCH]

    const int b  = blockIdx.z;
    const int r0 = blockIdx.y * TR;
    const int c0 = blockIdx.x * TC_T;
    const float* xpb = g_xp   + (size_t)b * NNODES * CCH;
    const float* asb = g_asrc + (size_t)b * NNODES * HEADS;
    const float* adb = g_adst + (size_t)b * NNODES * HEADS;

    for (int t = threadIdx.x; t < HNODES * 32; t += AGG_THREADS) {
        const int row = t >> 5;
        const int pos = (t & 31) << 2;
        const int hr = row / HC, hc = row - hr * HC;
        const int rg = r0 - 1 + hr, cg = c0 - 1 + hc;
        float4 v = {0.f, 0.f, 0.f, 0.f};
        if ((unsigned)rg < HH && (unsigned)cg < WWID)
            v = *(const float4*)&xpb[(size_t)(rg * WWID + cg) * CCH + pos];
        *(float4*)&s_xp[row * 128 + pos] = v;
    }
    for (int t = threadIdx.x; t < HNODES * 8; t += AGG_THREADS) {
        const int row = t >> 3;
        const int hr = row / HC, hc = row - hr * HC;
        const int rg = r0 - 1 + hr, cg = c0 - 1 + hc;
        float v = 0.f;
        if ((unsigned)rg < HH && (unsigned)cg < WWID)
            v = asb[(rg * WWID + cg) * HEADS + (t & 7)];
        s_as[t] = v;
    }
    for (int t = threadIdx.x; t < TNODES * 8; t += AGG_THREADS) {
        const int node = t >> 3;
        const int lr = node >> 3, lc = node & 7;
        s_ad[t] = adb[((r0 + lr) * WWID + c0 + lc) * HEADS + (t & 7)];
    }
    __syncthreads();

    const int warp = threadIdx.x >> 5;
    const int lane = threadIdx.x & 31;
    const int h    = lane >> 2;
    const int cch  = lane << 2;

    const float4 bv = *(const float4*)&bias[cch];
    const float4 gv = *(const float4*)&gamma[cch];
    const float4 be = *(const float4*)&beta[cch];

    const bool interior = (r0 > 0) && (r0 < HH - TR) && (c0 > 0) && (c0 < WWID - TC_T);
    if (interior) {
#pragma unroll 1
        for (int i = 0; i < 4; ++i) {
            const int nl = warp * 4 + i;
            const int lr = nl >> 3, lc = nl & 7;
            agg_node<false>(nl, lr, lc, r0 + lr, c0 + lc,
                            s_as, s_ad, s_xp, s_out, h, cch, bv, gv, be);
        }
    } else {
#pragma unroll 1
        for (int i = 0; i < 4; ++i) {
            const int nl = warp * 4 + i;
            const int lr = nl >> 3, lc = nl & 7;
            agg_node<true>(nl, lr, lc, r0 + lr, c0 + lc,
                           s_as, s_ad, s_xp, s_out, h, cch, bv, gv, be);
        }
    }
    __syncthreads();

    // ---- transposed store: float4 LDS (conflict-free) + 4 plane-strided STGs ----
    float* ob = out + (size_t)b * CCH * NNODES + (size_t)r0 * WWID + c0;
#pragma unroll
    for (int g = 0; g < 4; ++g) {
        const int t = threadIdx.x + AGG_THREADS * g;   // 0..2047
        const int node = t & 63;
        const int cg   = t >> 6;                       // channel group 0..31
        const float4 v = *(const float4*)&s_out[node * OPITCH + cg * 4];
        const int lr = node >> 3, lc = node & 7;
        float* p = ob + (size_t)(cg * 4) * NNODES + lr * WWID + lc;
        p[0]          = v.x;
        p[NNODES]     = v.y;
        p[2 * NNODES] = v.z;
        p[3 * NNODES] = v.w;
    }
}

// ---------------- launch ----------------
extern "C" void kernel_launch(void* const* d_in, const int* in_sizes, int n_in,
                              void* d_out, int out_size) {
    const float* x       = (const float*)d_in[0];
    const float* Wl      = (const float*)d_in[1];
    const float* att_src = (const float*)d_in[2];
    const float* att_dst = (const float*)d_in[3];
    const float* bias    = (const float*)d_in[4];
    const float* gamma   = (const float*)d_in[5];
    const float* beta    = (const float*)d_in[6];
    float* out = (float*)d_out;

    cudaFuncSetAttribute(mma_k, cudaFuncAttributeMaxDynamicSharedMemorySize, SMEM_MMA);
    cudaFuncSetAttribute(agg_k, cudaFuncAttributeMaxDynamicSharedMemorySize, SMEM_AGG);

    bprep_k<<<32, 256>>>(Wl);
    mma_k<<<dim3(NNODES / 128, BATCH), 256, SMEM_MMA>>>(x, att_src, att_dst);
    agg_k<<<dim3(WWID / TC_T, HH / TR, BATCH), AGG_THREADS, SMEM_AGG>>>(bias, gamma, beta, out);
}